// round 10
// baseline (speedup 1.0000x reference)
#include <cuda_runtime.h>
#include <math.h>

// Problem constants (fixed by setup_inputs)
#define BB      4
#define CDIM    64
#define HH      128
#define WWID    128
#define HW      (HH * WWID)
#define DD      256
#define NBOX    100
#define MAXDET  10
#define TOPK    5
#define CONF_T  0.2f
#define IOU_T   0.4f

// Output packing (flattened concat, float32):
//   seg_output : (H*W, B, 1) -> 65536
//   mask_maps  : (B, H, W)   -> 65536
//   kept       : (B, 10, 5)  -> 200
//   valid      : (B, 10)     -> 40
#define SEG_OFF   0
#define MASK_OFF  (HW * BB)
#define KEPT_OFF  (MASK_OFF + BB * HW)
#define VALID_OFF (KEPT_OFF + BB * MAXDET * 5)

#define TILE    12          // pixels per MLP block
#define PPG     6           // pixels per pixel-group
#define NTHR    512         // (2 pixel-groups x 2 k-halves) x 128 j-pairs
#define NBOXTOT (BB * MAXDET)                 // 40
#define CHUNKS  ((17 * 17 + TILE - 1) / TILE) // 25 chunks cover max box area
#define BOXBLK  (NBOXTOT * CHUNKS)            // 1000 box-MLP blocks (first)
#define MASKBLK (BB * HW / NTHR)              // 128 mask blocks (last)

// Device scratch (no dynamic allocation allowed)
__device__ float g_seg0;
__device__ int   g_box[NBOXTOT * 5];  // x1,y1,x2,y2,valid per kept box

// ---------------------------------------------------------------------------
// Kernel 1: blocks 0..3 = warp-level NMS per batch (warp 0 only, no barriers);
// block 4 = split-K zero-input MLP scalar (1024 threads).
// ---------------------------------------------------------------------------
__global__ __launch_bounds__(1024)
void nms_seg0_kernel(const float* __restrict__ boxes,
                     const float* __restrict__ W2,
                     const float* __restrict__ b1v,
                     const float* __restrict__ b2v,
                     const float* __restrict__ W3,
                     const float* __restrict__ b3v,
                     float* __restrict__ out, int out_size) {
    const int t = threadIdx.x;
    const unsigned FULL = 0xffffffffu;

    if (blockIdx.x == BB) {
        // ---- seg0 = MLP(0): 4 k-quarters x 256 neurons ----
        __shared__ __align__(16) float h1s[DD];
        __shared__ __align__(16) float partial[4][DD];
        __shared__ float red[8];
        const int j  = t & 255;
        const int kq = t >> 8;     // 0..3
        if (t < DD) h1s[t] = fmaxf(b1v[t], 0.f);
        __syncthreads();

        const float* Wp = W2 + (kq * 64) * DD + j;
        float acc = 0.f;
        #pragma unroll 8
        for (int k = 0; k < 64; k++)
            acc += h1s[kq * 64 + k] * Wp[k * DD];
        partial[kq][j] = acc;
        __syncthreads();

        if (kq == 0) {
            float h = partial[0][j] + partial[1][j] + partial[2][j]
                    + partial[3][j] + b2v[j];
            float v = fmaxf(h, 0.f) * W3[j];
            #pragma unroll
            for (int off = 16; off > 0; off >>= 1)
                v += __shfl_down_sync(FULL, v, off);
            if ((t & 31) == 0) red[t >> 5] = v;
        }
        __syncthreads();
        if (t == 0) {
            float s = b3v[0];
            #pragma unroll
            for (int w = 0; w < 8; w++) s += red[w];
            g_seg0 = s;
        }
        return;
    }

    // ---- warp-level NMS for batch b (warp 0 only, register-resident) ----
    if (t >= 32) return;
    const int b = blockIdx.x;
    const int l = t;

    float x1r[4], y1r[4], x2r[4], y2r[4], cfr[4], arr[4];
    bool  cd[4];

    #pragma unroll
    for (int i = 0; i < 4; i++) {
        int gi = l + 32 * i;
        if (gi < NBOX) {
            const float* bp = boxes + (b * NBOX + gi) * 5;
            x1r[i] = bp[0]; y1r[i] = bp[1];
            x2r[i] = bp[2]; y2r[i] = bp[3];
            cfr[i] = bp[4];
            arr[i] = fmaxf(x2r[i] - x1r[i], 0.f) * fmaxf(y2r[i] - y1r[i], 0.f);
        } else {
            x1r[i] = y1r[i] = x2r[i] = y2r[i] = 0.f;
            cfr[i] = -INFINITY; arr[i] = 0.f;
        }
    }

    bool lp = false;
    #pragma unroll
    for (int i = 0; i < 4; i++)
        if (l + 32 * i < NBOX && cfr[i] > CONF_T) lp = true;
    const bool anyp = __any_sync(FULL, lp);

    #pragma unroll
    for (int i = 0; i < 4; i++) {
        int gi = l + 32 * i;
        cd[i] = (gi < NBOX) ? (anyp ? (cfr[i] > CONF_T) : true) : false;
    }

    for (int it = 0; it < MAXDET; it++) {
        float s = -INFINITY; int idx = l;
        #pragma unroll
        for (int i = 0; i < 4; i++) {
            int gi = l + 32 * i;
            if (gi < NBOX && cd[i] && cfr[i] > s) { s = cfr[i]; idx = gi; }
        }
        #pragma unroll
        for (int off = 16; off > 0; off >>= 1) {
            float s2 = __shfl_xor_sync(FULL, s, off);
            int   i2 = __shfl_xor_sync(FULL, idx, off);
            if (s2 > s || (s2 == s && i2 < idx)) { s = s2; idx = i2; }
        }
        const bool has = (s > -INFINITY);

        const int src = idx & 31, slot = idx >> 5;
        float q0 = x1r[0], q1 = y1r[0], q2 = x2r[0], q3 = y2r[0],
              q4 = cfr[0], qa = arr[0];
        if (slot == 1) { q0=x1r[1]; q1=y1r[1]; q2=x2r[1]; q3=y2r[1]; q4=cfr[1]; qa=arr[1]; }
        if (slot == 2) { q0=x1r[2]; q1=y1r[2]; q2=x2r[2]; q3=y2r[2]; q4=cfr[2]; qa=arr[2]; }
        if (slot == 3) { q0=x1r[3]; q1=y1r[3]; q2=x2r[3]; q3=y2r[3]; q4=cfr[3]; qa=arr[3]; }
        const float X1 = __shfl_sync(FULL, q0, src);
        const float Y1 = __shfl_sync(FULL, q1, src);
        const float X2 = __shfl_sync(FULL, q2, src);
        const float Y2 = __shfl_sync(FULL, q3, src);
        const float CF = __shfl_sync(FULL, q4, src);
        const float AR = __shfl_sync(FULL, qa, src);

        if (has) {
            #pragma unroll
            for (int i = 0; i < 4; i++) {
                int gi = l + 32 * i;
                if (gi < NBOX && cd[i]) {
                    float lt0 = fmaxf(X1, x1r[i]);
                    float lt1 = fmaxf(Y1, y1r[i]);
                    float rb0 = fminf(X2, x2r[i]);
                    float rb1 = fminf(Y2, y2r[i]);
                    float iw = fmaxf(rb0 - lt0, 0.f);
                    float ih = fmaxf(rb1 - lt1, 0.f);
                    float inter = iw * ih;
                    float iou = inter / (AR + arr[i] - inter + 1e-9f);
                    if (iou > IOU_T) cd[i] = false;
                    if (gi == idx) cd[i] = false;
                }
            }
        }

        if (l == it) {
            int ko = KEPT_OFF + (b * MAXDET + it) * 5;
            if (ko + 4 < out_size) {
                out[ko + 0] = X1; out[ko + 1] = Y1;
                out[ko + 2] = X2; out[ko + 3] = Y2;
                out[ko + 4] = CF;
            }
            bool v = has && (X2 - X1 >= 1.f) && (Y2 - Y1 >= 1.f)
                     && (anyp ? true : (it < TOPK));
            int ix1 = min(max((int)floorf(X1 + 0.5f), 0), WWID);
            int iy1 = min(max((int)floorf(Y1 + 0.5f), 0), HH);
            int ix2 = min(max((int)floorf(X2 + 0.5f), 0), WWID);
            int iy2 = min(max((int)floorf(Y2 + 0.5f), 0), HH);
            int base = (b * MAXDET + it) * 5;
            g_box[base + 0] = ix1;
            g_box[base + 1] = iy1;
            g_box[base + 2] = ix2;
            g_box[base + 3] = iy2;
            g_box[base + 4] = v ? 1 : 0;
            int vo = VALID_OFF + b * MAXDET + it;
            if (vo < out_size) out[vo] = v ? 1.f : 0.f;
        }
    }
}

// ---------------------------------------------------------------------------
// Half-K partial GEMM, n=2 neurons per thread (adjacent pair):
//   acc[p].x += act[p][k] * W[k][j0],  acc[p].y += act[p][k] * W[k][j0+1]
// 4-deep double-buffered float2 weight prefetch.
// ---------------------------------------------------------------------------
template<int STRIDE>
__device__ __forceinline__ void mm2(const float* __restrict__ Wp,  // &W[khoff][j0]
                                    const float* __restrict__ act,
                                    int klen, float initx, float inity,
                                    float2 acc[PPG]) {
    #pragma unroll
    for (int p = 0; p < PPG; p++) { acc[p].x = initx; acc[p].y = inity; }
    float2 w[4], wn[4];
    #pragma unroll
    for (int i = 0; i < 4; i++) w[i] = *(const float2*)&Wp[i * DD];
    #pragma unroll 1
    for (int k0 = 0; k0 < klen - 4; k0 += 4) {
        #pragma unroll
        for (int i = 0; i < 4; i++) wn[i] = *(const float2*)&Wp[(k0 + 4 + i) * DD];
        #pragma unroll
        for (int p = 0; p < PPG; p++) {
            float4 v = *(const float4*)&act[p * STRIDE + k0];
            acc[p].x += v.x * w[0].x + v.y * w[1].x + v.z * w[2].x + v.w * w[3].x;
            acc[p].y += v.x * w[0].y + v.y * w[1].y + v.z * w[2].y + v.w * w[3].y;
        }
        #pragma unroll
        for (int i = 0; i < 4; i++) w[i] = wn[i];
    }
    {
        const int k0 = klen - 4;
        #pragma unroll
        for (int p = 0; p < PPG; p++) {
            float4 v = *(const float4*)&act[p * STRIDE + k0];
            acc[p].x += v.x * w[0].x + v.y * w[1].x + v.z * w[2].x + v.w * w[3].x;
            acc[p].y += v.x * w[0].y + v.y * w[1].y + v.z * w[2].y + v.w * w[3].y;
        }
    }
}

// ---------------------------------------------------------------------------
// Kernel 2 (fused, two roles, disjoint output pixels):
//   blocks [0, BOXBLK): box-MLP role — block = (box bi, chunk ci).
//   blocks [BOXBLK, +MASKBLK): mask role (short; tail-fills the wave).
// Thread layout (box role): 512 = (2 pixel-groups x 2 k-halves) x 128 j-pairs.
// ---------------------------------------------------------------------------
__global__ __launch_bounds__(NTHR)
void work_kernel(const float* __restrict__ x,
                 const float* __restrict__ W_sem, const float* __restrict__ b_sem,
                 const float* __restrict__ W1, const float* __restrict__ b1,
                 const float* __restrict__ W2, const float* __restrict__ b2,
                 const float* __restrict__ W3, const float* __restrict__ b3,
                 float* __restrict__ out, int out_size) {
    const int t = threadIdx.x;

    if (blockIdx.x >= BOXBLK) {
        // ---- mask role ----
        int id = (blockIdx.x - BOXBLK) * NTHR + t;
        int b = id / HW, pix = id % HW;
        int h = pix / WWID, w = pix % WWID;

        bool inside = false;
        #pragma unroll
        for (int d = 0; d < MAXDET; d++) {
            int base = (b * MAXDET + d) * 5;
            int vx1 = g_box[base + 0], vy1 = g_box[base + 1];
            int vx2 = g_box[base + 2], vy2 = g_box[base + 3];
            int vv  = g_box[base + 4];
            if (vv && w >= vx1 && w < vx2 && h >= vy1 && h < vy2) inside = true;
        }

        int mo = MASK_OFF + id;
        if (mo < out_size) out[mo] = inside ? 0.f : 1.f;
        if (!inside) {                       // inside pixels written by MLP role
            int so = SEG_OFF + pix * BB + b;
            if (so < out_size) out[so] = g_seg0;
        }
        return;
    }

    // ---- box-MLP role ----
    const int bi = blockIdx.x / CHUNKS;   // kept-box index 0..39
    const int ci = blockIdx.x % CHUNKS;   // pixel chunk within box

    __shared__ __align__(16) float xs[TILE][CDIM];   // gathered x    (3 KB)
    __shared__ __align__(16) float ws[TILE][DD];     // activations   (12 KB)
    __shared__ __align__(16) float part[TILE][DD];   // k-half partials (12 KB)
    __shared__ __align__(16) int   sbox[8];
    __shared__ int   plist[TILE];
    __shared__ float wred[8][PPG];

    if (t < 5) sbox[t] = g_box[bi * 5 + t];
    __syncthreads();

    const int bx1 = sbox[0], by1 = sbox[1];
    const int bw  = sbox[2] - bx1, bh = sbox[3] - by1;
    const int tot = (sbox[4] && bw > 0 && bh > 0) ? bw * bh : 0;
    if (ci * TILE >= tot) return;      // uniform across block

    const int bidx = bi / MAXDET;      // batch

    if (t < TILE) {
        int q = ci * TILE + t;
        plist[t] = (q < tot)
                 ? (bidx * HW + (by1 + q / bw) * WWID + (bx1 + q % bw))
                 : -1;
    }
    __syncthreads();

    const int jj = t & 127;        // j-pair index: neurons 2jj, 2jj+1
    const int j0 = 2 * jj;
    const int g  = t >> 7;         // 0..3
    const int pg = g & 1;          // pixel group
    const int kh = g >> 1;         // k-half
    const int pb = pg * PPG;       // pixel base

    // gather x[b, :, pix] -> xs[p][c]   (768 elements; p fastest for coalescing)
    #pragma unroll
    for (int i = t; i < TILE * CDIM; i += NTHR) {
        int p = i % TILE, c = i / TILE;
        int id = plist[p];
        float v = 0.f;
        if (id >= 0) {
            int b = id / HW, pix = id % HW;
            v = x[(b * CDIM + c) * HW + pix];
        }
        xs[p][c] = v;
    }
    __syncthreads();

    float2 acc[PPG];

    // ---- seman: words = xs @ W_sem + b_sem   (K=64, split 32/32)
    mm2<CDIM>(W_sem + kh * 32 * DD + j0, &xs[pb][kh * 32], 32,
              kh == 0 ? b_sem[j0] : 0.f, kh == 0 ? b_sem[j0 + 1] : 0.f, acc);
    if (kh == 1) {
        #pragma unroll
        for (int p = 0; p < PPG; p++) *(float2*)&part[pb + p][j0] = acc[p];
    }
    __syncthreads();
    if (kh == 0) {
        #pragma unroll
        for (int p = 0; p < PPG; p++) {
            float2 pr = *(const float2*)&part[pb + p][j0];
            float2 r; r.x = acc[p].x + pr.x; r.y = acc[p].y + pr.y;
            *(float2*)&ws[pb + p][j0] = r;     // no relu on seman
        }
    }
    __syncthreads();

    // ---- layer 1: h1 = relu(words @ W1 + b1)   (K=256, split 128/128)
    mm2<DD>(W1 + kh * 128 * DD + j0, &ws[pb][kh * 128], 128,
            kh == 0 ? b1[j0] : 0.f, kh == 0 ? b1[j0 + 1] : 0.f, acc);
    if (kh == 1) {
        #pragma unroll
        for (int p = 0; p < PPG; p++) *(float2*)&part[pb + p][j0] = acc[p];
    }
    __syncthreads();   // partials visible AND all ws reads complete
    if (kh == 0) {
        #pragma unroll
        for (int p = 0; p < PPG; p++) {
            float2 pr = *(const float2*)&part[pb + p][j0];
            float2 r;
            r.x = fmaxf(acc[p].x + pr.x, 0.f);
            r.y = fmaxf(acc[p].y + pr.y, 0.f);
            *(float2*)&ws[pb + p][j0] = r;
        }
    }
    __syncthreads();

    // ---- layer 2: h2 = relu(h1 @ W2 + b2)   (K=256, split 128/128)
    mm2<DD>(W2 + kh * 128 * DD + j0, &ws[pb][kh * 128], 128,
            kh == 0 ? b2[j0] : 0.f, kh == 0 ? b2[j0 + 1] : 0.f, acc);
    if (kh == 1) {
        #pragma unroll
        for (int p = 0; p < PPG; p++) *(float2*)&part[pb + p][j0] = acc[p];
    }
    __syncthreads();

    // ---- layer 3 (kh==0, t<256): seg[p] = sum_j relu(h2)*W3[j] + b3
    if (kh == 0) {
        float2 w3 = *(const float2*)&W3[j0];
        int lane = t & 31, warp = t >> 5;   // warp in [0,8)
        #pragma unroll
        for (int p = 0; p < PPG; p++) {
            float2 pr = *(const float2*)&part[pb + p][j0];
            float v = fmaxf(acc[p].x + pr.x, 0.f) * w3.x
                    + fmaxf(acc[p].y + pr.y, 0.f) * w3.y;
            #pragma unroll
            for (int off = 16; off > 0; off >>= 1)
                v += __shfl_down_sync(0xffffffffu, v, off);
            if (lane == 0) wred[warp][p] = v;
        }
    }
    __syncthreads();
    if (t < TILE) {
        int og = t / PPG;             // owning pixel-group (4 warps each)
        int lp = t - og * PPG;
        float s = b3[0];
        #pragma unroll
        for (int w4 = 0; w4 < 4; w4++) s += wred[og * 4 + w4][lp];
        int id = plist[t];
        if (id >= 0) {
            int b = id / HW, pix = id % HW;
            int so = SEG_OFF + pix * BB + b;
            if (so < out_size) out[so] = s;
        }
    }
}

// ---------------------------------------------------------------------------
extern "C" void kernel_launch(void* const* d_in, const int* in_sizes, int n_in,
                              void* d_out, int out_size) {
    const float* x      = (const float*)d_in[0];
    const float* rboxes = (const float*)d_in[1];
    const float* W_sem  = (const float*)d_in[2];
    const float* b_sem  = (const float*)d_in[3];
    const float* W1     = (const float*)d_in[4];
    const float* b1     = (const float*)d_in[5];
    const float* W2     = (const float*)d_in[6];
    const float* b2     = (const float*)d_in[7];
    const float* W3     = (const float*)d_in[8];
    const float* b3     = (const float*)d_in[9];
    float* out = (float*)d_out;

    nms_seg0_kernel<<<BB + 1, 1024>>>(rboxes, W2, b1, b2, W3, b3, out, out_size);
    work_kernel<<<BOXBLK + MASKBLK, NTHR>>>(x, W_sem, b_sem,
                                            W1, b1, W2, b2, W3, b3,
                                            out, out_size);
}

// round 11
// speedup vs baseline: 1.0631x; 1.0631x over previous
#include <cuda_runtime.h>
#include <math.h>

// Problem constants (fixed by setup_inputs)
#define BB      4
#define CDIM    64
#define HH      128
#define WWID    128
#define HW      (HH * WWID)
#define DD      256
#define NBOX    100
#define MAXDET  10
#define TOPK    5
#define CONF_T  0.2f
#define IOU_T   0.4f

// Output packing (flattened concat, float32):
//   seg_output : (H*W, B, 1) -> 65536
//   mask_maps  : (B, H, W)   -> 65536
//   kept       : (B, 10, 5)  -> 200
//   valid      : (B, 10)     -> 40
#define SEG_OFF   0
#define MASK_OFF  (HW * BB)
#define KEPT_OFF  (MASK_OFF + BB * HW)
#define VALID_OFF (KEPT_OFF + BB * MAXDET * 5)

#define TILE    12          // pixels per MLP block
#define PPG     3           // pixels per pixel-group (4 groups)
#define NTHR    512         // (4 pixel-groups x 2 k-halves) x 64 j-quads
#define NBOXTOT (BB * MAXDET)                 // 40
#define CHUNKS  ((17 * 17 + TILE - 1) / TILE) // 25 chunks cover max box area
#define BOXBLK  (NBOXTOT * CHUNKS)            // 1000 box-MLP blocks (first)
#define MASKBLK (BB * HW / NTHR)              // 128 mask blocks (last)

// Device scratch (no dynamic allocation allowed)
__device__ float g_seg0;
__device__ int   g_box[NBOXTOT * 5];  // x1,y1,x2,y2,valid per kept box

// ---------------------------------------------------------------------------
// Kernel 1: blocks 0..3 = warp-level NMS per batch (warp 0 only, no barriers);
// block 4 = split-K zero-input MLP scalar (1024 threads).
// ---------------------------------------------------------------------------
__global__ __launch_bounds__(1024)
void nms_seg0_kernel(const float* __restrict__ boxes,
                     const float* __restrict__ W2,
                     const float* __restrict__ b1v,
                     const float* __restrict__ b2v,
                     const float* __restrict__ W3,
                     const float* __restrict__ b3v,
                     float* __restrict__ out, int out_size) {
    const int t = threadIdx.x;
    const unsigned FULL = 0xffffffffu;

    if (blockIdx.x == BB) {
        // ---- seg0 = MLP(0): 4 k-quarters x 256 neurons ----
        __shared__ __align__(16) float h1s[DD];
        __shared__ __align__(16) float partial[4][DD];
        __shared__ float red[8];
        const int j  = t & 255;
        const int kq = t >> 8;     // 0..3
        if (t < DD) h1s[t] = fmaxf(b1v[t], 0.f);
        __syncthreads();

        const float* Wp = W2 + (kq * 64) * DD + j;
        float acc = 0.f;
        #pragma unroll 8
        for (int k = 0; k < 64; k++)
            acc += h1s[kq * 64 + k] * Wp[k * DD];
        partial[kq][j] = acc;
        __syncthreads();

        if (kq == 0) {
            float h = partial[0][j] + partial[1][j] + partial[2][j]
                    + partial[3][j] + b2v[j];
            float v = fmaxf(h, 0.f) * W3[j];
            #pragma unroll
            for (int off = 16; off > 0; off >>= 1)
                v += __shfl_down_sync(FULL, v, off);
            if ((t & 31) == 0) red[t >> 5] = v;
        }
        __syncthreads();
        if (t == 0) {
            float s = b3v[0];
            #pragma unroll
            for (int w = 0; w < 8; w++) s += red[w];
            g_seg0 = s;
        }
        return;
    }

    // ---- warp-level NMS for batch b (warp 0 only, register-resident) ----
    if (t >= 32) return;
    const int b = blockIdx.x;
    const int l = t;

    float x1r[4], y1r[4], x2r[4], y2r[4], cfr[4], arr[4];
    bool  cd[4];

    #pragma unroll
    for (int i = 0; i < 4; i++) {
        int gi = l + 32 * i;
        if (gi < NBOX) {
            const float* bp = boxes + (b * NBOX + gi) * 5;
            x1r[i] = bp[0]; y1r[i] = bp[1];
            x2r[i] = bp[2]; y2r[i] = bp[3];
            cfr[i] = bp[4];
            arr[i] = fmaxf(x2r[i] - x1r[i], 0.f) * fmaxf(y2r[i] - y1r[i], 0.f);
        } else {
            x1r[i] = y1r[i] = x2r[i] = y2r[i] = 0.f;
            cfr[i] = -INFINITY; arr[i] = 0.f;
        }
    }

    bool lp = false;
    #pragma unroll
    for (int i = 0; i < 4; i++)
        if (l + 32 * i < NBOX && cfr[i] > CONF_T) lp = true;
    const bool anyp = __any_sync(FULL, lp);

    #pragma unroll
    for (int i = 0; i < 4; i++) {
        int gi = l + 32 * i;
        cd[i] = (gi < NBOX) ? (anyp ? (cfr[i] > CONF_T) : true) : false;
    }

    for (int it = 0; it < MAXDET; it++) {
        float s = -INFINITY; int idx = l;
        #pragma unroll
        for (int i = 0; i < 4; i++) {
            int gi = l + 32 * i;
            if (gi < NBOX && cd[i] && cfr[i] > s) { s = cfr[i]; idx = gi; }
        }
        #pragma unroll
        for (int off = 16; off > 0; off >>= 1) {
            float s2 = __shfl_xor_sync(FULL, s, off);
            int   i2 = __shfl_xor_sync(FULL, idx, off);
            if (s2 > s || (s2 == s && i2 < idx)) { s = s2; idx = i2; }
        }
        const bool has = (s > -INFINITY);

        const int src = idx & 31, slot = idx >> 5;
        float q0 = x1r[0], q1 = y1r[0], q2 = x2r[0], q3 = y2r[0],
              q4 = cfr[0], qa = arr[0];
        if (slot == 1) { q0=x1r[1]; q1=y1r[1]; q2=x2r[1]; q3=y2r[1]; q4=cfr[1]; qa=arr[1]; }
        if (slot == 2) { q0=x1r[2]; q1=y1r[2]; q2=x2r[2]; q3=y2r[2]; q4=cfr[2]; qa=arr[2]; }
        if (slot == 3) { q0=x1r[3]; q1=y1r[3]; q2=x2r[3]; q3=y2r[3]; q4=cfr[3]; qa=arr[3]; }
        const float X1 = __shfl_sync(FULL, q0, src);
        const float Y1 = __shfl_sync(FULL, q1, src);
        const float X2 = __shfl_sync(FULL, q2, src);
        const float Y2 = __shfl_sync(FULL, q3, src);
        const float CF = __shfl_sync(FULL, q4, src);
        const float AR = __shfl_sync(FULL, qa, src);

        if (has) {
            #pragma unroll
            for (int i = 0; i < 4; i++) {
                int gi = l + 32 * i;
                if (gi < NBOX && cd[i]) {
                    float lt0 = fmaxf(X1, x1r[i]);
                    float lt1 = fmaxf(Y1, y1r[i]);
                    float rb0 = fminf(X2, x2r[i]);
                    float rb1 = fminf(Y2, y2r[i]);
                    float iw = fmaxf(rb0 - lt0, 0.f);
                    float ih = fmaxf(rb1 - lt1, 0.f);
                    float inter = iw * ih;
                    float iou = inter / (AR + arr[i] - inter + 1e-9f);
                    if (iou > IOU_T) cd[i] = false;
                    if (gi == idx) cd[i] = false;
                }
            }
        }

        if (l == it) {
            int ko = KEPT_OFF + (b * MAXDET + it) * 5;
            if (ko + 4 < out_size) {
                out[ko + 0] = X1; out[ko + 1] = Y1;
                out[ko + 2] = X2; out[ko + 3] = Y2;
                out[ko + 4] = CF;
            }
            bool v = has && (X2 - X1 >= 1.f) && (Y2 - Y1 >= 1.f)
                     && (anyp ? true : (it < TOPK));
            int ix1 = min(max((int)floorf(X1 + 0.5f), 0), WWID);
            int iy1 = min(max((int)floorf(Y1 + 0.5f), 0), HH);
            int ix2 = min(max((int)floorf(X2 + 0.5f), 0), WWID);
            int iy2 = min(max((int)floorf(Y2 + 0.5f), 0), HH);
            int base = (b * MAXDET + it) * 5;
            g_box[base + 0] = ix1;
            g_box[base + 1] = iy1;
            g_box[base + 2] = ix2;
            g_box[base + 3] = iy2;
            g_box[base + 4] = v ? 1 : 0;
            int vo = VALID_OFF + b * MAXDET + it;
            if (vo < out_size) out[vo] = v ? 1.f : 0.f;
        }
    }
}

// ---------------------------------------------------------------------------
// Half-K partial GEMM, n=4 neurons per thread (adjacent quad, LDG.128):
//   acc[p].{x,y,z,w} += act[p][k] * W[k][j0..j0+3]
// 4-k iterations: 4 LDG.128 (weights) + 3 broadcast LDS.128 (act) per 48 FMA.
// ---------------------------------------------------------------------------
template<int STRIDE>
__device__ __forceinline__ void mm4(const float* __restrict__ Wp,  // &W[khoff][j0]
                                    const float* __restrict__ act,
                                    int klen, float4 init, float4 acc[PPG]) {
    #pragma unroll
    for (int p = 0; p < PPG; p++) acc[p] = init;
    #pragma unroll 1
    for (int k0 = 0; k0 < klen; k0 += 4) {
        float4 w0 = *(const float4*)&Wp[(k0 + 0) * DD];
        float4 w1 = *(const float4*)&Wp[(k0 + 1) * DD];
        float4 w2 = *(const float4*)&Wp[(k0 + 2) * DD];
        float4 w3 = *(const float4*)&Wp[(k0 + 3) * DD];
        #pragma unroll
        for (int p = 0; p < PPG; p++) {
            float4 a = *(const float4*)&act[p * STRIDE + k0];
            acc[p].x += a.x * w0.x + a.y * w1.x + a.z * w2.x + a.w * w3.x;
            acc[p].y += a.x * w0.y + a.y * w1.y + a.z * w2.y + a.w * w3.y;
            acc[p].z += a.x * w0.z + a.y * w1.z + a.z * w2.z + a.w * w3.z;
            acc[p].w += a.x * w0.w + a.y * w1.w + a.z * w2.w + a.w * w3.w;
        }
    }
}

__device__ __forceinline__ float4 f4add(float4 a, float4 b) {
    float4 r; r.x = a.x + b.x; r.y = a.y + b.y; r.z = a.z + b.z; r.w = a.w + b.w;
    return r;
}

// ---------------------------------------------------------------------------
// Kernel 2 (fused, two roles, disjoint output pixels):
//   blocks [0, BOXBLK): box-MLP role — block = (box bi, chunk ci).
//   blocks [BOXBLK, +MASKBLK): mask role (short; tail-fills the wave).
// Thread layout (box role): 512 = (4 pixel-groups x 2 k-halves) x 64 j-quads.
// ---------------------------------------------------------------------------
__global__ __launch_bounds__(NTHR)
void work_kernel(const float* __restrict__ x,
                 const float* __restrict__ W_sem, const float* __restrict__ b_sem,
                 const float* __restrict__ W1, const float* __restrict__ b1,
                 const float* __restrict__ W2, const float* __restrict__ b2,
                 const float* __restrict__ W3, const float* __restrict__ b3,
                 float* __restrict__ out, int out_size) {
    const int t = threadIdx.x;

    if (blockIdx.x >= BOXBLK) {
        // ---- mask role ----
        int id = (blockIdx.x - BOXBLK) * NTHR + t;
        int b = id / HW, pix = id % HW;
        int h = pix / WWID, w = pix % WWID;

        bool inside = false;
        #pragma unroll
        for (int d = 0; d < MAXDET; d++) {
            int base = (b * MAXDET + d) * 5;
            int vx1 = g_box[base + 0], vy1 = g_box[base + 1];
            int vx2 = g_box[base + 2], vy2 = g_box[base + 3];
            int vv  = g_box[base + 4];
            if (vv && w >= vx1 && w < vx2 && h >= vy1 && h < vy2) inside = true;
        }

        int mo = MASK_OFF + id;
        if (mo < out_size) out[mo] = inside ? 0.f : 1.f;
        if (!inside) {                       // inside pixels written by MLP role
            int so = SEG_OFF + pix * BB + b;
            if (so < out_size) out[so] = g_seg0;
        }
        return;
    }

    // ---- box-MLP role ----
    const int bi = blockIdx.x / CHUNKS;   // kept-box index 0..39
    const int ci = blockIdx.x % CHUNKS;   // pixel chunk within box

    __shared__ __align__(16) float xs[TILE][CDIM];   // gathered x    (3 KB)
    __shared__ __align__(16) float ws[TILE][DD];     // activations   (12 KB)
    __shared__ __align__(16) float part[TILE][DD];   // k-half partials (12 KB)
    __shared__ __align__(16) int   sbox[8];
    __shared__ int   plist[TILE];
    __shared__ float wred[8][PPG];

    if (t < 5) sbox[t] = g_box[bi * 5 + t];
    __syncthreads();

    const int bx1 = sbox[0], by1 = sbox[1];
    const int bw  = sbox[2] - bx1, bh = sbox[3] - by1;
    const int tot = (sbox[4] && bw > 0 && bh > 0) ? bw * bh : 0;
    if (ci * TILE >= tot) return;      // uniform across block

    const int bidx = bi / MAXDET;      // batch

    if (t < TILE) {
        int q = ci * TILE + t;
        plist[t] = (q < tot)
                 ? (bidx * HW + (by1 + q / bw) * WWID + (bx1 + q % bw))
                 : -1;
    }
    __syncthreads();

    const int jq = t & 63;         // j-quad index: neurons 4jq..4jq+3
    const int j0 = 4 * jq;
    const int g  = t >> 6;         // 0..7
    const int pg = g & 3;          // pixel group (4 of them)
    const int kh = g >> 2;         // k-half
    const int pb = pg * PPG;       // pixel base

    // gather x[b, :, pix] -> xs[p][c]   (768 elements; p fastest for coalescing)
    #pragma unroll
    for (int i = t; i < TILE * CDIM; i += NTHR) {
        int p = i % TILE, c = i / TILE;
        int id = plist[p];
        float v = 0.f;
        if (id >= 0) {
            int b = id / HW, pix = id % HW;
            v = x[(b * CDIM + c) * HW + pix];
        }
        xs[p][c] = v;
    }
    __syncthreads();

    const float4 zero4 = make_float4(0.f, 0.f, 0.f, 0.f);
    float4 acc[PPG];

    // ---- seman: words = xs @ W_sem + b_sem   (K=64, split 32/32)
    mm4<CDIM>(W_sem + kh * 32 * DD + j0, &xs[pb][kh * 32], 32,
              kh == 0 ? *(const float4*)&b_sem[j0] : zero4, acc);
    if (kh == 1) {
        #pragma unroll
        for (int p = 0; p < PPG; p++) *(float4*)&part[pb + p][j0] = acc[p];
    }
    __syncthreads();
    if (kh == 0) {
        #pragma unroll
        for (int p = 0; p < PPG; p++) {
            float4 pr = *(const float4*)&part[pb + p][j0];
            *(float4*)&ws[pb + p][j0] = f4add(acc[p], pr);   // no relu on seman
        }
    }
    __syncthreads();

    // ---- layer 1: h1 = relu(words @ W1 + b1)   (K=256, split 128/128)
    mm4<DD>(W1 + kh * 128 * DD + j0, &ws[pb][kh * 128], 128,
            kh == 0 ? *(const float4*)&b1[j0] : zero4, acc);
    if (kh == 1) {
        #pragma unroll
        for (int p = 0; p < PPG; p++) *(float4*)&part[pb + p][j0] = acc[p];
    }
    __syncthreads();   // partials visible AND all ws reads complete
    if (kh == 0) {
        #pragma unroll
        for (int p = 0; p < PPG; p++) {
            float4 pr = *(const float4*)&part[pb + p][j0];
            float4 r = f4add(acc[p], pr);
            r.x = fmaxf(r.x, 0.f); r.y = fmaxf(r.y, 0.f);
            r.z = fmaxf(r.z, 0.f); r.w = fmaxf(r.w, 0.f);
            *(float4*)&ws[pb + p][j0] = r;
        }
    }
    __syncthreads();

    // ---- layer 2: h2 = relu(h1 @ W2 + b2)   (K=256, split 128/128)
    mm4<DD>(W2 + kh * 128 * DD + j0, &ws[pb][kh * 128], 128,
            kh == 0 ? *(const float4*)&b2[j0] : zero4, acc);
    if (kh == 1) {
        #pragma unroll
        for (int p = 0; p < PPG; p++) *(float4*)&part[pb + p][j0] = acc[p];
    }
    __syncthreads();

    // ---- layer 3 (kh==0, t<256): seg[p] = sum_j relu(h2)*W3[j] + b3
    if (kh == 0) {
        float4 w3 = *(const float4*)&W3[j0];
        int lane = t & 31, warp = t >> 5;   // warp in [0,8)
        #pragma unroll
        for (int p = 0; p < PPG; p++) {
            float4 pr = *(const float4*)&part[pb + p][j0];
            float4 h = f4add(acc[p], pr);
            float v = fmaxf(h.x, 0.f) * w3.x + fmaxf(h.y, 0.f) * w3.y
                    + fmaxf(h.z, 0.f) * w3.z + fmaxf(h.w, 0.f) * w3.w;
            #pragma unroll
            for (int off = 16; off > 0; off >>= 1)
                v += __shfl_down_sync(0xffffffffu, v, off);
            if (lane == 0) wred[warp][p] = v;
        }
    }
    __syncthreads();
    if (t < TILE) {
        int og = t / PPG;             // owning pixel-group (2 warps each)
        int lp = t - og * PPG;
        float s = b3[0] + wred[og * 2][lp] + wred[og * 2 + 1][lp];
        int id = plist[t];
        if (id >= 0) {
            int b = id / HW, pix = id % HW;
            int so = SEG_OFF + pix * BB + b;
            if (so < out_size) out[so] = s;
        }
    }
}

// ---------------------------------------------------------------------------
extern "C" void kernel_launch(void* const* d_in, const int* in_sizes, int n_in,
                              void* d_out, int out_size) {
    const float* x      = (const float*)d_in[0];
    const float* rboxes = (const float*)d_in[1];
    const float* W_sem  = (const float*)d_in[2];
    const float* b_sem  = (const float*)d_in[3];
    const float* W1     = (const float*)d_in[4];
    const float* b1     = (const float*)d_in[5];
    const float* W2     = (const float*)d_in[6];
    const float* b2     = (const float*)d_in[7];
    const float* W3     = (const float*)d_in[8];
    const float* b3     = (const float*)d_in[9];
    float* out = (float*)d_out;

    nms_seg0_kernel<<<BB + 1, 1024>>>(rboxes, W2, b1, b2, W3, b3, out, out_size);
    work_kernel<<<BOXBLK + MASKBLK, NTHR>>>(x, W_sem, b_sem,
                                            W1, b1, W2, b2, W3, b3,
                                            out, out_size);
}